// round 9
// baseline (speedup 1.0000x reference)
#include <cuda_runtime.h>

#define BATCH 32
#define LSEQ  2048
#define DDIM  1024
#define NVOC  320
#define SPLIT 64
#define LSEG  (LSEQ / SPLIT)   // 32

// ---------------------------------------------------------------------------
// Fused kernel: per-(split,b) block redundantly computes its batch's
// histogram + weight-sum, streams its 32-row feature segment, and reduces
// its normalized partial straight into `out` via red.global.v4.f32.
// SPLIT=64 -> ~1.7 waves: late blocks' prologues overlap early blocks'
// streams, shrinking both exposed-prologue and tail-spread losses.
// vq_indices / input_lengths are int32 (JAX x64-disabled downcast).
// ---------------------------------------------------------------------------
#define JL      (LSEQ / 256)   // 8 l-values per thread
#define PF_LINES 3             // 3 x 128B lines/thread = rows 0..23 of segment

__global__ void __launch_bounds__(256)
gemv_fused_kernel(const float* __restrict__ feat,
                  const int*   __restrict__ lengths,
                  const int*   __restrict__ vq,
                  float*       __restrict__ out)
{
    __shared__ int   s_cx[NVOC];
    __shared__ int   s_cy[NVOC];
    __shared__ float s_p[LSEQ];     // unnormalized per-position weights
    __shared__ float s_red[8];
    __shared__ float s_inv;

    const int split = blockIdx.x;   // 0..SPLIT-1
    const int b     = blockIdx.y;   // 0..BATCH-1
    const int tid   = threadIdx.x;  // 0..255

    // Segment base: input_feature[b, 1, split*LSEG, :]  (N=2, take last)
    const float* seg = feat + ((size_t)b * 2 + 1) * (size_t)LSEQ * DDIM
                            + (size_t)split * LSEG * DDIM;

    // ---- Phase 0: L2 prefetch of rows 0..23 (96 KB/block) -----------------
    {
        const char* pf = reinterpret_cast<const char*>(seg) + (size_t)tid * 128;
#pragma unroll
        for (int i = 0; i < PF_LINES; i++)
            asm volatile("prefetch.global.L2 [%0];"
                         :: "l"(pf + (size_t)i * 256 * 128) : "memory");
    }

    // ---- Phase A: histogram (full batch, redundant per split) ----
    // NVOC=320 > blockDim=256: MUST stride (R5 lesson: stale smem on replay).
    for (int i = tid; i < NVOC; i += 256) { s_cx[i] = 0; s_cy[i] = 0; }
    __syncthreads();

    // vq as int4: two (x,y) pairs per 16B load.
    const int4* vq4 = reinterpret_cast<const int4*>(vq) + (size_t)b * (LSEQ / 2);
    int ix[JL], iy[JL];
#pragma unroll
    for (int j = 0; j < JL / 2; j++) {
        int4 v = vq4[tid + j * 256];
        ix[2*j]   = v.x;  iy[2*j]   = v.y;
        ix[2*j+1] = v.z;  iy[2*j+1] = v.w;
        atomicAdd(&s_cx[v.x], 1);
        atomicAdd(&s_cy[v.y], 1);
        atomicAdd(&s_cx[v.z], 1);
        atomicAdd(&s_cy[v.w], 1);
    }
    __syncthreads();

    // ---- Phase B: per-position p = mask / freq, block sum -> 1/sum ----
    // int4 layout: thread handles positions 2*(tid + j*256) and +1.
    const int len = lengths[b];
    float lsum = 0.0f;
#pragma unroll
    for (int j = 0; j < JL / 2; j++) {
        const int l0 = 2 * (tid + j * 256);
        float p0 = 0.0f, p1 = 0.0f;
        if (l0 < len)
            p0 = __fdividef(1.0f, (float)(s_cx[ix[2*j]] + s_cy[iy[2*j]]));
        if (l0 + 1 < len)
            p1 = __fdividef(1.0f, (float)(s_cx[ix[2*j+1]] + s_cy[iy[2*j+1]]));
        s_p[l0]     = p0;
        s_p[l0 + 1] = p1;
        lsum += p0 + p1;
    }
#pragma unroll
    for (int o = 16; o > 0; o >>= 1) lsum += __shfl_xor_sync(0xffffffffu, lsum, o);
    if ((tid & 31) == 0) s_red[tid >> 5] = lsum;
    __syncthreads();
    if (tid < 8) {
        float s = s_red[tid];
#pragma unroll
        for (int o = 4; o > 0; o >>= 1) s += __shfl_xor_sync(0xffu, s, o);
        if (tid == 0) s_inv = __fdividef(1.0f, s);
    }
    __syncthreads();

    // ---- Phase C: stream the LSEG-row feature segment, weighted by p ----
    const float4* f4 = reinterpret_cast<const float4*>(seg) + tid;
    const float*  pw = &s_p[split * LSEG];

    float4 acc = make_float4(0.f, 0.f, 0.f, 0.f);
#pragma unroll
    for (int l = 0; l < LSEG; l++) {
        const float  w = pw[l];
        const float4 v = __ldcs(f4 + (size_t)l * (DDIM / 4));
        acc.x = fmaf(w, v.x, acc.x);
        acc.y = fmaf(w, v.y, acc.y);
        acc.z = fmaf(w, v.z, acc.z);
        acc.w = fmaf(w, v.w, acc.w);
    }

    const float inv = s_inv;
    acc.x *= inv; acc.y *= inv; acc.z *= inv; acc.w *= inv;

    // ---- Phase D: vector reduction straight into the output ----
    float* dst = out + (size_t)b * DDIM + tid * 4;
    asm volatile("red.global.add.v4.f32 [%0], {%1, %2, %3, %4};"
                 :: "l"(dst), "f"(acc.x), "f"(acc.y), "f"(acc.z), "f"(acc.w)
                 : "memory");
}

// ---------------------------------------------------------------------------
extern "C" void kernel_launch(void* const* d_in, const int* in_sizes, int n_in,
                              void* d_out, int out_size)
{
    const float* feat    = (const float*)d_in[0];
    const int*   lengths = (const int*)d_in[1];
    const int*   vq      = (const int*)d_in[2];
    float*       out     = (float*)d_out;

    (void)in_sizes; (void)n_in;

    // Output is poisoned before timing and accumulated via atomics: zero it.
    cudaMemsetAsync(out, 0, (size_t)out_size * sizeof(float));
    gemv_fused_kernel<<<dim3(SPLIT, BATCH), 256>>>(feat, lengths, vq, out);
}

// round 10
// speedup vs baseline: 1.0912x; 1.0912x over previous
#include <cuda_runtime.h>

#define BATCH 32
#define LSEQ  2048
#define DDIM  1024
#define NVOC  320
#define SPLIT 32
#define LSEG  (LSEQ / SPLIT)   // 64

// ---------------------------------------------------------------------------
// Fused kernel: per-(split,b) block redundantly computes its batch's
// histogram + weight-sum, streams its 64-row feature segment, and reduces
// its normalized partial straight into `out` via red.global.v4.f32.
// SPLIT=32 (single wave) — R9 showed the prologue is a fixed per-block cost,
// so more/smaller blocks REGRESS. Prologue latency is hidden by (a) L2
// prefetch of the first 24 segment rows, (b) hoisting vq loads above the
// histogram zeroing.
// vq_indices / input_lengths are int32 (JAX x64-disabled downcast).
// ---------------------------------------------------------------------------
#define JL       (LSEQ / 256)  // 8 l-values per thread
#define PF_LINES 3             // 3 x 128B lines/thread = rows 0..23 of segment

__global__ void __launch_bounds__(256)
gemv_fused_kernel(const float* __restrict__ feat,
                  const int*   __restrict__ lengths,
                  const int*   __restrict__ vq,
                  float*       __restrict__ out)
{
    __shared__ int   s_cx[NVOC];
    __shared__ int   s_cy[NVOC];
    __shared__ float s_p[LSEQ];     // unnormalized per-position weights
    __shared__ float s_red[8];
    __shared__ float s_inv;

    const int split = blockIdx.x;   // 0..SPLIT-1
    const int b     = blockIdx.y;   // 0..BATCH-1
    const int tid   = threadIdx.x;  // 0..255

    // Segment base: input_feature[b, 1, split*LSEG, :]  (N=2, take last)
    const float* seg = feat + ((size_t)b * 2 + 1) * (size_t)LSEQ * DDIM
                            + (size_t)split * LSEG * DDIM;

    // ---- Phase 0: L2 prefetch of rows 0..23 (96 KB/block) -----------------
    {
        const char* pf = reinterpret_cast<const char*>(seg) + (size_t)tid * 128;
#pragma unroll
        for (int i = 0; i < PF_LINES; i++)
            asm volatile("prefetch.global.L2 [%0];"
                         :: "l"(pf + (size_t)i * 256 * 128) : "memory");
    }

    // ---- Hoisted vq loads: overlap their latency with histogram zeroing ---
    const int4* vq4 = reinterpret_cast<const int4*>(vq) + (size_t)b * (LSEQ / 2);
    int4 vr[JL / 2];
#pragma unroll
    for (int j = 0; j < JL / 2; j++)
        vr[j] = vq4[tid + j * 256];

    // ---- Phase A: histogram (full batch, redundant per split) ----
    // NVOC=320 > blockDim=256: MUST stride (R5 lesson: stale smem on replay).
    for (int i = tid; i < NVOC; i += 256) { s_cx[i] = 0; s_cy[i] = 0; }
    __syncthreads();

#pragma unroll
    for (int j = 0; j < JL / 2; j++) {
        atomicAdd(&s_cx[vr[j].x], 1);
        atomicAdd(&s_cy[vr[j].y], 1);
        atomicAdd(&s_cx[vr[j].z], 1);
        atomicAdd(&s_cy[vr[j].w], 1);
    }
    __syncthreads();

    // ---- Phase B: per-position p = mask / freq, block sum -> 1/sum ----
    // int4 layout: thread handles positions 2*(tid + j*256) and +1.
    const int len = lengths[b];
    float lsum = 0.0f;
#pragma unroll
    for (int j = 0; j < JL / 2; j++) {
        const int l0 = 2 * (tid + j * 256);
        float p0 = 0.0f, p1 = 0.0f;
        if (l0 < len)
            p0 = __fdividef(1.0f, (float)(s_cx[vr[j].x] + s_cy[vr[j].y]));
        if (l0 + 1 < len)
            p1 = __fdividef(1.0f, (float)(s_cx[vr[j].z] + s_cy[vr[j].w]));
        s_p[l0]     = p0;
        s_p[l0 + 1] = p1;
        lsum += p0 + p1;
    }
#pragma unroll
    for (int o = 16; o > 0; o >>= 1) lsum += __shfl_xor_sync(0xffffffffu, lsum, o);
    if ((tid & 31) == 0) s_red[tid >> 5] = lsum;
    __syncthreads();
    if (tid < 8) {
        float s = s_red[tid];
#pragma unroll
        for (int o = 4; o > 0; o >>= 1) s += __shfl_xor_sync(0xffu, s, o);
        if (tid == 0) s_inv = __fdividef(1.0f, s);
    }
    __syncthreads();

    // ---- Phase C: stream the 64-row feature segment, weighted by p ----
    const float4* f4 = reinterpret_cast<const float4*>(seg) + tid;
    const float*  pw = &s_p[split * LSEG];

    float4 acc = make_float4(0.f, 0.f, 0.f, 0.f);
#pragma unroll 16
    for (int l = 0; l < LSEG; l++) {
        const float  w = pw[l];
        const float4 v = __ldcs(f4 + (size_t)l * (DDIM / 4));
        acc.x = fmaf(w, v.x, acc.x);
        acc.y = fmaf(w, v.y, acc.y);
        acc.z = fmaf(w, v.z, acc.z);
        acc.w = fmaf(w, v.w, acc.w);
    }

    const float inv = s_inv;
    acc.x *= inv; acc.y *= inv; acc.z *= inv; acc.w *= inv;

    // ---- Phase D: vector reduction straight into the output ----
    float* dst = out + (size_t)b * DDIM + tid * 4;
    asm volatile("red.global.add.v4.f32 [%0], {%1, %2, %3, %4};"
                 :: "l"(dst), "f"(acc.x), "f"(acc.y), "f"(acc.z), "f"(acc.w)
                 : "memory");
}

// ---------------------------------------------------------------------------
extern "C" void kernel_launch(void* const* d_in, const int* in_sizes, int n_in,
                              void* d_out, int out_size)
{
    const float* feat    = (const float*)d_in[0];
    const int*   lengths = (const int*)d_in[1];
    const int*   vq      = (const int*)d_in[2];
    float*       out     = (float*)d_out;

    (void)in_sizes; (void)n_in;

    // Output is poisoned before timing and accumulated via atomics: zero it.
    cudaMemsetAsync(out, 0, (size_t)out_size * sizeof(float));
    gemv_fused_kernel<<<dim3(SPLIT, BATCH), 256>>>(feat, lengths, vq, out);
}

// round 11
// speedup vs baseline: 1.0988x; 1.0069x over previous
#include <cuda_runtime.h>

#define BATCH 32
#define LSEQ  2048
#define DDIM  1024
#define NVOC  320
#define SPLIT 16
#define LSEG  (LSEQ / SPLIT)   // 128
#define NTHR  512

// ---------------------------------------------------------------------------
// Fused kernel: per-(split,b) block redundantly computes its batch's
// histogram + weight-sum, streams its 128-row feature segment, and reduces
// its normalized partial straight into `out` via red.global.v4.f32.
// SPLIT=16 x 512thr: half the redundant prologue work of R8 (R9 lesson:
// prologue is a fixed per-block cost), same chip-wide warp count for the
// stream (4 blocks/SM x 16 warps = 64 warps/SM).
// vq_indices / input_lengths are int32 (JAX x64-disabled downcast).
// ---------------------------------------------------------------------------
#define JL       (LSEQ / NTHR)  // 4 l-values per thread
#define PF_LINES 3              // 3 x 128B lines/thread = rows 0..47 of segment

__global__ void __launch_bounds__(NTHR)
gemv_fused_kernel(const float* __restrict__ feat,
                  const int*   __restrict__ lengths,
                  const int*   __restrict__ vq,
                  float*       __restrict__ out)
{
    __shared__ int   s_cx[NVOC];
    __shared__ int   s_cy[NVOC];
    __shared__ float s_p[LSEQ];     // unnormalized per-position weights
    __shared__ float s_red[NTHR / 32];
    __shared__ float s_inv;

    const int split = blockIdx.x;   // 0..SPLIT-1
    const int b     = blockIdx.y;   // 0..BATCH-1
    const int tid   = threadIdx.x;  // 0..511

    // Segment base: input_feature[b, 1, split*LSEG, :]  (N=2, take last)
    const float* seg = feat + ((size_t)b * 2 + 1) * (size_t)LSEQ * DDIM
                            + (size_t)split * LSEG * DDIM;

    // ---- Phase 0: L2 prefetch of rows 0..47 (192 KB/block, 96 MB chip) ----
    {
        const char* pf = reinterpret_cast<const char*>(seg) + (size_t)tid * 128;
#pragma unroll
        for (int i = 0; i < PF_LINES; i++)
            asm volatile("prefetch.global.L2 [%0];"
                         :: "l"(pf + (size_t)i * NTHR * 128) : "memory");
    }

    // ---- Hoisted vq loads (int4: two (x,y) pairs per 16B) ------------------
    const int4* vq4 = reinterpret_cast<const int4*>(vq) + (size_t)b * (LSEQ / 2);
    int4 vr[JL / 2];
#pragma unroll
    for (int j = 0; j < JL / 2; j++)
        vr[j] = vq4[tid + j * NTHR];

    // ---- Phase A: histogram (full batch, redundant per split) ----
    if (tid < NVOC) { s_cx[tid] = 0; s_cy[tid] = 0; }   // NTHR=512 > NVOC=320
    __syncthreads();

#pragma unroll
    for (int j = 0; j < JL / 2; j++) {
        atomicAdd(&s_cx[vr[j].x], 1);
        atomicAdd(&s_cy[vr[j].y], 1);
        atomicAdd(&s_cx[vr[j].z], 1);
        atomicAdd(&s_cy[vr[j].w], 1);
    }
    __syncthreads();

    // ---- Phase B: per-position p = mask / freq, block sum -> 1/sum ----
    const int len = lengths[b];
    float lsum = 0.0f;
#pragma unroll
    for (int j = 0; j < JL / 2; j++) {
        const int l0 = 2 * (tid + j * NTHR);
        float p0 = 0.0f, p1 = 0.0f;
        if (l0 < len)
            p0 = __fdividef(1.0f, (float)(s_cx[vr[j].x] + s_cy[vr[j].y]));
        if (l0 + 1 < len)
            p1 = __fdividef(1.0f, (float)(s_cx[vr[j].z] + s_cy[vr[j].w]));
        s_p[l0]     = p0;
        s_p[l0 + 1] = p1;
        lsum += p0 + p1;
    }
#pragma unroll
    for (int o = 16; o > 0; o >>= 1) lsum += __shfl_xor_sync(0xffffffffu, lsum, o);
    if ((tid & 31) == 0) s_red[tid >> 5] = lsum;
    __syncthreads();
    if (tid < NTHR / 32) {   // 16 partials
        float s = s_red[tid];
#pragma unroll
        for (int o = 8; o > 0; o >>= 1) s += __shfl_xor_sync(0xffffu, s, o);
        if (tid == 0) s_inv = __fdividef(1.0f, s);
    }
    __syncthreads();

    // ---- Phase C: stream the 128-row segment, split over two thread-halves.
    // dlane = tid & 255 (float4 lane of D), half = tid >> 8 selects rows.
    const int dlane = tid & 255;
    const int half  = tid >> 8;           // 0 or 1
    const int rbase = half * (LSEG / 2);  // 0 or 64

    const float4* f4 = reinterpret_cast<const float4*>(seg)
                       + (size_t)rbase * (DDIM / 4) + dlane;
    const float*  pw = &s_p[split * LSEG + rbase];

    float4 acc = make_float4(0.f, 0.f, 0.f, 0.f);
#pragma unroll 16
    for (int l = 0; l < LSEG / 2; l++) {
        const float  w = pw[l];
        const float4 v = __ldcs(f4 + (size_t)l * (DDIM / 4));
        acc.x = fmaf(w, v.x, acc.x);
        acc.y = fmaf(w, v.y, acc.y);
        acc.z = fmaf(w, v.z, acc.z);
        acc.w = fmaf(w, v.w, acc.w);
    }

    const float inv = s_inv;
    acc.x *= inv; acc.y *= inv; acc.z *= inv; acc.w *= inv;

    // ---- Phase D: vector reduction straight into the output ----
    // Both halves add to the same addresses; red.global is atomic.
    float* dst = out + (size_t)b * DDIM + dlane * 4;
    asm volatile("red.global.add.v4.f32 [%0], {%1, %2, %3, %4};"
                 :: "l"(dst), "f"(acc.x), "f"(acc.y), "f"(acc.z), "f"(acc.w)
                 : "memory");
}

// ---------------------------------------------------------------------------
extern "C" void kernel_launch(void* const* d_in, const int* in_sizes, int n_in,
                              void* d_out, int out_size)
{
    const float* feat    = (const float*)d_in[0];
    const int*   lengths = (const int*)d_in[1];
    const int*   vq      = (const int*)d_in[2];
    float*       out     = (float*)d_out;

    (void)in_sizes; (void)n_in;

    // Output is poisoned before timing and accumulated via atomics: zero it.
    cudaMemsetAsync(out, 0, (size_t)out_size * sizeof(float));
    gemv_fused_kernel<<<dim3(SPLIT, BATCH), NTHR>>>(feat, lengths, vq, out);
}

// round 12
// speedup vs baseline: 1.2899x; 1.1739x over previous
#include <cuda_runtime.h>

#define BATCH 32
#define LSEQ  2048
#define DDIM  1024
#define NVOC  320
#define SPLIT 16
#define LSEG  (LSEQ / SPLIT)   // 128
#define NTHR  512

// ---------------------------------------------------------------------------
// Fused kernel (R12): skip masked rows. Positions l >= len have weight 0,
// so their 4KB feature rows are never loaded (cuts ~25% of HBM traffic).
// Blocks entirely beyond len exit immediately. Otherwise identical to R11:
// redundant per-block histogram + weight-sum, stream live rows, red.global
// into out. vq_indices / input_lengths are int32 (JAX x64 downcast).
// ---------------------------------------------------------------------------
#define JL       (LSEQ / NTHR)  // 4 l-values per thread
#define PF_LINES 3              // up to 3 x 128B lines/thread (clamped to live)

__global__ void __launch_bounds__(NTHR)
gemv_fused_kernel(const float* __restrict__ feat,
                  const int*   __restrict__ lengths,
                  const int*   __restrict__ vq,
                  float*       __restrict__ out)
{
    __shared__ int   s_cx[NVOC];
    __shared__ int   s_cy[NVOC];
    __shared__ float s_p[LSEQ];     // unnormalized per-position weights
    __shared__ float s_red[NTHR / 32];
    __shared__ float s_inv;

    const int split = blockIdx.x;   // 0..SPLIT-1
    const int b     = blockIdx.y;   // 0..BATCH-1
    const int tid   = threadIdx.x;  // 0..511

    // Mask-aware early exit: this block's segment contributes nothing.
    const int len       = lengths[b];
    const int seg_start = split * LSEG;
    if (seg_start >= len) return;
    const int rows_eff  = min(LSEG, len - seg_start);

    // Segment base: input_feature[b, 1, seg_start, :]  (N=2, take last)
    const float* seg = feat + ((size_t)b * 2 + 1) * (size_t)LSEQ * DDIM
                            + (size_t)seg_start * DDIM;

    // ---- Phase 0: L2 prefetch of leading LIVE rows --------------------------
    {
        const size_t live_bytes = (size_t)rows_eff * DDIM * 4;
        const char*  base = reinterpret_cast<const char*>(seg);
#pragma unroll
        for (int i = 0; i < PF_LINES; i++) {
            const size_t off = ((size_t)tid + (size_t)i * NTHR) * 128;
            if (off < live_bytes)
                asm volatile("prefetch.global.L2 [%0];"
                             :: "l"(base + off) : "memory");
        }
    }

    // ---- Hoisted vq loads (int4: two (x,y) pairs per 16B) -------------------
    const int4* vq4 = reinterpret_cast<const int4*>(vq) + (size_t)b * (LSEQ / 2);
    int4 vr[JL / 2];
#pragma unroll
    for (int j = 0; j < JL / 2; j++)
        vr[j] = vq4[tid + j * NTHR];

    // ---- Phase A: histogram over ALL positions (reference is unmasked) ----
    if (tid < NVOC) { s_cx[tid] = 0; s_cy[tid] = 0; }   // NTHR=512 > NVOC=320
    __syncthreads();

#pragma unroll
    for (int j = 0; j < JL / 2; j++) {
        atomicAdd(&s_cx[vr[j].x], 1);
        atomicAdd(&s_cy[vr[j].y], 1);
        atomicAdd(&s_cx[vr[j].z], 1);
        atomicAdd(&s_cy[vr[j].w], 1);
    }
    __syncthreads();

    // ---- Phase B: per-position p = mask / freq, block sum -> 1/sum ----
    float lsum = 0.0f;
#pragma unroll
    for (int j = 0; j < JL / 2; j++) {
        const int l0 = 2 * (tid + j * NTHR);
        float p0 = 0.0f, p1 = 0.0f;
        if (l0 < len)
            p0 = __fdividef(1.0f, (float)(s_cx[vr[j].x] + s_cy[vr[j].y]));
        if (l0 + 1 < len)
            p1 = __fdividef(1.0f, (float)(s_cx[vr[j].z] + s_cy[vr[j].w]));
        s_p[l0]     = p0;
        s_p[l0 + 1] = p1;
        lsum += p0 + p1;
    }
#pragma unroll
    for (int o = 16; o > 0; o >>= 1) lsum += __shfl_xor_sync(0xffffffffu, lsum, o);
    if ((tid & 31) == 0) s_red[tid >> 5] = lsum;
    __syncthreads();
    if (tid < NTHR / 32) {   // 16 partials
        float s = s_red[tid];
#pragma unroll
        for (int o = 8; o > 0; o >>= 1) s += __shfl_xor_sync(0xffffu, s, o);
        if (tid == 0) s_inv = __fdividef(1.0f, s);
    }
    __syncthreads();

    // ---- Phase C: stream LIVE rows, split over two thread-halves ----------
    // dlane = tid & 255 (float4 lane of D); halves interleave rows by parity
    // so a partial segment stays balanced between the halves.
    const int dlane = tid & 255;
    const int half  = tid >> 8;           // 0 or 1

    const float4* f4 = reinterpret_cast<const float4*>(seg)
                       + (size_t)half * (DDIM / 4) + dlane;
    const float*  pw = &s_p[seg_start + half];

    float4 acc = make_float4(0.f, 0.f, 0.f, 0.f);
#pragma unroll 8
    for (int l = half; l < rows_eff; l += 2) {
        const float  w = pw[l - half];
        const float4 v = __ldcs(f4 + (size_t)(l - half) * (DDIM / 4));
        acc.x = fmaf(w, v.x, acc.x);
        acc.y = fmaf(w, v.y, acc.y);
        acc.z = fmaf(w, v.z, acc.z);
        acc.w = fmaf(w, v.w, acc.w);
    }

    const float inv = s_inv;
    acc.x *= inv; acc.y *= inv; acc.z *= inv; acc.w *= inv;

    // ---- Phase D: vector reduction straight into the output ----------------
    float* dst = out + (size_t)b * DDIM + dlane * 4;
    asm volatile("red.global.add.v4.f32 [%0], {%1, %2, %3, %4};"
                 :: "l"(dst), "f"(acc.x), "f"(acc.y), "f"(acc.z), "f"(acc.w)
                 : "memory");
}

// ---------------------------------------------------------------------------
extern "C" void kernel_launch(void* const* d_in, const int* in_sizes, int n_in,
                              void* d_out, int out_size)
{
    const float* feat    = (const float*)d_in[0];
    const int*   lengths = (const int*)d_in[1];
    const int*   vq      = (const int*)d_in[2];
    float*       out     = (float*)d_out;

    (void)in_sizes; (void)n_in;

    // Output is poisoned before timing and accumulated via atomics: zero it.
    cudaMemsetAsync(out, 0, (size_t)out_size * sizeof(float));
    gemv_fused_kernel<<<dim3(SPLIT, BATCH), NTHR>>>(feat, lengths, vq, out);
}